// round 2
// baseline (speedup 1.0000x reference)
#include <cuda_runtime.h>
#include <math.h>

#define BATCH   2
#define SEQ     1024
#define DMODEL  1024
#define DINNER  2048
#define DTRANK  64
#define DSTATE  16
#define DCONV   4
#define ROWS    (BATCH*SEQ)            // 2048
#define XPROJ_OUT (DTRANK + 2*DSTATE)  // 96

typedef unsigned long long ull;

__device__ __forceinline__ void ffma2(ull &d, ull a, ull b) {
    asm("fma.rn.f32x2 %0, %1, %2, %0;" : "+l"(d) : "l"(a), "l"(b));
}
__device__ __forceinline__ ull pack_dup(float x) {
    ull r; asm("mov.b64 %0, {%1, %1};" : "=l"(r) : "f"(x)); return r;
}
__device__ __forceinline__ float2 unpack2(ull v) {
    float2 f; asm("mov.b64 {%0, %1}, %2;" : "=f"(f.x), "=f"(f.y) : "l"(v)); return f;
}

// ---------------- scratch (static device globals; no allocation) ------------
__device__ float g_xn   [ROWS*DMODEL];
__device__ float g_xz   [ROWS*2*DINNER];
__device__ float g_u    [ROWS*DINNER];
__device__ float g_xdbl [ROWS*XPROJ_OUT];
__device__ float g_delta[ROWS*DINNER];
__device__ float g_yg   [ROWS*DINNER];

// ---------------- LayerNorm: one block per row ------------------------------
__global__ void ln_kernel(const float* __restrict__ x, const float* __restrict__ g,
                          const float* __restrict__ b, float* __restrict__ out)
{
    int row = blockIdx.x;
    int tid = threadIdx.x;
    const float* xr = x + (size_t)row*DMODEL;
    float v[4];
    float s1 = 0.f, s2 = 0.f;
    #pragma unroll
    for (int i = 0; i < 4; i++) {
        v[i] = xr[tid + 256*i];
        s1 += v[i];
        s2 += v[i]*v[i];
    }
    __shared__ float sh1[8], sh2[8];
    #pragma unroll
    for (int o = 16; o; o >>= 1) {
        s1 += __shfl_xor_sync(0xffffffffu, s1, o);
        s2 += __shfl_xor_sync(0xffffffffu, s2, o);
    }
    if ((tid & 31) == 0) { sh1[tid>>5] = s1; sh2[tid>>5] = s2; }
    __syncthreads();
    if (tid < 32) {
        float a = (tid < 8) ? sh1[tid] : 0.f;
        float c = (tid < 8) ? sh2[tid] : 0.f;
        #pragma unroll
        for (int o = 4; o; o >>= 1) {
            a += __shfl_xor_sync(0xffffffffu, a, o);
            c += __shfl_xor_sync(0xffffffffu, c, o);
        }
        if (tid == 0) { sh1[0] = a; sh2[0] = c; }
    }
    __syncthreads();
    float mu  = sh1[0] * (1.f/DMODEL);
    float var = sh2[0] * (1.f/DMODEL) - mu*mu;
    float r   = rsqrtf(var + 1e-5f);
    float* o = out + (size_t)row*DMODEL;
    #pragma unroll
    for (int i = 0; i < 4; i++) {
        int c = tid + 256*i;
        o[c] = (v[i]-mu)*r*g[c] + b[c];
    }
}

// ---------------- SGEMM NT with f32x2 packed FMA ----------------------------
// C[M,N] = A[M,K] * B[N,K]^T, epilogue modes:
//   0: plain store, 1: += R (residual), 2: softplus(v + bias[n])
#define BM 128
#define BN 128
#define BKT 8

__global__ __launch_bounds__(256, 2) void sgemm_nt(
    const float* __restrict__ A, int lda,
    const float* __restrict__ B, int ldb,
    float* __restrict__ C, int ldc,
    const float* __restrict__ R, int ldr,
    const float* __restrict__ bias,
    int M, int N, int K, int mode)
{
    __shared__ float As[BKT][BM+4];
    __shared__ float Bs[BKT][BN+4];

    int tid = threadIdx.x;
    int tx  = tid & 15;   // 0..15
    int ty  = tid >> 4;   // 0..15
    int m0  = blockIdx.y * BM;
    int n0  = blockIdx.x * BN;

    int lrow = tid >> 1;         // 0..127
    int lk4  = (tid & 1) * 4;    // 0 / 4

    ull acc2[8][4];
    #pragma unroll
    for (int i = 0; i < 8; i++)
        #pragma unroll
        for (int j = 0; j < 4; j++) acc2[i][j] = 0ull;

    for (int k0 = 0; k0 < K; k0 += BKT) {
        float4 a = make_float4(0.f,0.f,0.f,0.f);
        int am = m0 + lrow;
        if (am < M) a = *reinterpret_cast<const float4*>(A + (size_t)am*lda + k0 + lk4);
        As[lk4+0][lrow] = a.x; As[lk4+1][lrow] = a.y;
        As[lk4+2][lrow] = a.z; As[lk4+3][lrow] = a.w;

        float4 bv = make_float4(0.f,0.f,0.f,0.f);
        int bn = n0 + lrow;
        if (bn < N) bv = *reinterpret_cast<const float4*>(B + (size_t)bn*ldb + k0 + lk4);
        Bs[lk4+0][lrow] = bv.x; Bs[lk4+1][lrow] = bv.y;
        Bs[lk4+2][lrow] = bv.z; Bs[lk4+3][lrow] = bv.w;

        __syncthreads();

        #pragma unroll
        for (int kk = 0; kk < BKT; kk++) {
            float4 a0 = *reinterpret_cast<const float4*>(&As[kk][ty*4]);
            float4 a1 = *reinterpret_cast<const float4*>(&As[kk][64 + ty*4]);
            ulonglong2 b0 = *reinterpret_cast<const ulonglong2*>(&Bs[kk][tx*4]);
            ulonglong2 b1 = *reinterpret_cast<const ulonglong2*>(&Bs[kk][64 + tx*4]);
            ull ra2[8];
            ra2[0] = pack_dup(a0.x); ra2[1] = pack_dup(a0.y);
            ra2[2] = pack_dup(a0.z); ra2[3] = pack_dup(a0.w);
            ra2[4] = pack_dup(a1.x); ra2[5] = pack_dup(a1.y);
            ra2[6] = pack_dup(a1.z); ra2[7] = pack_dup(a1.w);
            ull rb2[4] = {b0.x, b0.y, b1.x, b1.y};
            #pragma unroll
            for (int i = 0; i < 8; i++)
                #pragma unroll
                for (int j = 0; j < 4; j++)
                    ffma2(acc2[i][j], ra2[i], rb2[j]);
        }
        __syncthreads();
    }

    #pragma unroll
    for (int i = 0; i < 8; i++) {
        int m = m0 + ((i < 4) ? (ty*4 + i) : (64 + ty*4 + i - 4));
        if (m >= M) continue;
        #pragma unroll
        for (int j = 0; j < 4; j++) {
            int n = n0 + ((j < 2) ? (tx*4 + j*2) : (64 + tx*4 + (j-2)*2));
            if (n + 1 < N) {
                float2 v = unpack2(acc2[i][j]);
                if (mode == 1) {
                    v.x += R[(size_t)m*ldr + n];
                    v.y += R[(size_t)m*ldr + n + 1];
                } else if (mode == 2) {
                    float vx = v.x + bias[n];
                    float vy = v.y + bias[n+1];
                    v.x = (vx > 20.f) ? vx : log1pf(expf(vx));
                    v.y = (vy > 20.f) ? vy : log1pf(expf(vy));
                }
                *reinterpret_cast<float2*>(C + (size_t)m*ldc + n) = v;
            }
        }
    }
}

// ---------------- x_proj tall-skinny GEMM: [2048,96] = u[2048,2048] @ w^T ----
// BM=16 rows, full N=96, BK=32. 128 blocks. Packed f32x2.
#define XP_BM 16
#define XP_BK 32

__global__ __launch_bounds__(256) void xproj_kernel(
    const float* __restrict__ u, const float* __restrict__ w, float* __restrict__ xdbl)
{
    __shared__ float As[XP_BK][XP_BM];
    __shared__ float Bs[XP_BK][XPROJ_OUT];

    int tid = threadIdx.x;
    int m0  = blockIdx.x * XP_BM;
    int r   = tid >> 4;   // 0..15
    int cg  = tid & 15;   // 0..15 -> cols cg*6 .. cg*6+5

    ull acc2[3] = {0ull, 0ull, 0ull};

    for (int k0 = 0; k0 < DINNER; k0 += XP_BK) {
        #pragma unroll
        for (int e = tid; e < XP_BM*XP_BK; e += 256) {
            int k = e & 31, m = e >> 5;
            As[k][m] = u[(size_t)(m0+m)*DINNER + k0 + k];
        }
        #pragma unroll
        for (int e = tid; e < XPROJ_OUT*XP_BK; e += 256) {
            int k = e & 31, n = e >> 5;
            Bs[k][n] = w[(size_t)n*DINNER + k0 + k];
        }
        __syncthreads();
        #pragma unroll
        for (int kk = 0; kk < XP_BK; kk++) {
            ull a2 = pack_dup(As[kk][r]);
            const ull* bp = reinterpret_cast<const ull*>(&Bs[kk][cg*6]);
            ffma2(acc2[0], a2, bp[0]);
            ffma2(acc2[1], a2, bp[1]);
            ffma2(acc2[2], a2, bp[2]);
        }
        __syncthreads();
    }

    float* o = xdbl + (size_t)(m0 + r)*XPROJ_OUT + cg*6;
    *reinterpret_cast<float2*>(o+0) = unpack2(acc2[0]);
    *reinterpret_cast<float2*>(o+2) = unpack2(acc2[1]);
    *reinterpret_cast<float2*>(o+4) = unpack2(acc2[2]);
}

// ---------------- causal depthwise conv1d + SiLU ----------------------------
__global__ void conv_silu_kernel(const float* __restrict__ xz, const float* __restrict__ w,
                                 const float* __restrict__ bias, float* __restrict__ u)
{
    int i = blockIdx.x*blockDim.x + threadIdx.x;
    if (i >= ROWS*DINNER) return;
    int d    = i % DINNER;
    int row  = i / DINNER;       // b*SEQ + l
    int l    = row % SEQ;
    float acc = bias[d];
    #pragma unroll
    for (int t = 0; t < DCONV; t++) {
        int li = l + t - (DCONV-1);
        if (li >= 0)
            acc += xz[((size_t)(row + li - l))*(2*DINNER) + d] * w[d*DCONV + t];
    }
    float sig = 1.f / (1.f + expf(-acc));
    u[i] = acc * sig;
}

// ---------------- selective scan: 1 lane per (channel,state), gate fused ----
__global__ __launch_bounds__(256) void scan_kernel(
    const float* __restrict__ delta, const float* __restrict__ u,
    const float* __restrict__ xdbl, const float* __restrict__ xz,
    const float* __restrict__ A_log, const float* __restrict__ Dskip,
    float* __restrict__ yg)
{
    int warp = threadIdx.x >> 5;
    int lane = threadIdx.x & 31;
    int half = lane >> 4;
    int n    = lane & 15;
    int c    = blockIdx.x*16 + warp*2 + half;   // 0..4095
    int b    = c / DINNER;
    int d    = c % DINNER;

    float A  = -expf(A_log[d*DSTATE + n]);
    float Dd = Dskip[d];
    float h  = 0.f;

    const float* drow = delta + (size_t)b*SEQ*DINNER + d;
    const float* urow = u     + (size_t)b*SEQ*DINNER + d;
    const float* xrow = xdbl  + (size_t)b*SEQ*XPROJ_OUT;
    const float* zrow = xz    + (size_t)b*SEQ*(2*DINNER) + DINNER + d;
    float*       yrow = yg    + (size_t)b*SEQ*DINNER + d;

    for (int t = 0; t < SEQ; t++) {
        float dt = drow[(size_t)t*DINNER];
        float ut = urow[(size_t)t*DINNER];
        float Bn = xrow[t*XPROJ_OUT + DTRANK + n];
        float Cn = xrow[t*XPROJ_OUT + DTRANK + DSTATE + n];
        float dA = expf(dt * A);
        h = fmaf(dA, h, dt*ut*Bn);
        float p = h * Cn;
        p += __shfl_xor_sync(0xffffffffu, p, 8);
        p += __shfl_xor_sync(0xffffffffu, p, 4);
        p += __shfl_xor_sync(0xffffffffu, p, 2);
        p += __shfl_xor_sync(0xffffffffu, p, 1);
        if (n == 0) {
            float z = zrow[(size_t)t*(2*DINNER)];
            float s = z / (1.f + expf(-z));
            yrow[(size_t)t*DINNER] = fmaf(ut, Dd, p) * s;
        }
    }
}

// ---------------- launch ----------------------------------------------------
extern "C" void kernel_launch(void* const* d_in, const int* in_sizes, int n_in,
                              void* d_out, int out_size)
{
    const float* x      = (const float*)d_in[0];
    const float* ln_g   = (const float*)d_in[1];
    const float* ln_b   = (const float*)d_in[2];
    const float* w_in   = (const float*)d_in[3];
    const float* conv_w = (const float*)d_in[4];
    const float* conv_b = (const float*)d_in[5];
    const float* w_x    = (const float*)d_in[6];
    const float* w_dt   = (const float*)d_in[7];
    const float* b_dt   = (const float*)d_in[8];
    const float* A_log  = (const float*)d_in[9];
    const float* Dsk    = (const float*)d_in[10];
    const float* w_out  = (const float*)d_in[11];
    float* out = (float*)d_out;

    float *xn, *xz, *u, *xdbl, *delta, *yg;
    cudaGetSymbolAddress((void**)&xn,    g_xn);
    cudaGetSymbolAddress((void**)&xz,    g_xz);
    cudaGetSymbolAddress((void**)&u,     g_u);
    cudaGetSymbolAddress((void**)&xdbl,  g_xdbl);
    cudaGetSymbolAddress((void**)&delta, g_delta);
    cudaGetSymbolAddress((void**)&yg,    g_yg);

    int nelem = ROWS*DINNER;

    // 1. layernorm
    ln_kernel<<<ROWS, 256>>>(x, ln_g, ln_b, xn);

    // 2. in_proj: xz[2048,4096] = xn[2048,1024] @ w_in[4096,1024]^T
    {
        dim3 g(2*DINNER/BN, ROWS/BM);
        sgemm_nt<<<g, 256>>>(xn, DMODEL, w_in, DMODEL, xz, 2*DINNER,
                             nullptr, 0, nullptr, ROWS, 2*DINNER, DMODEL, 0);
    }

    // 3. causal depthwise conv + SiLU -> u
    conv_silu_kernel<<<(nelem+255)/256, 256>>>(xz, conv_w, conv_b, u);

    // 4. x_proj (tall-skinny): xdbl[2048,96] = u @ w_x[96,2048]^T
    xproj_kernel<<<ROWS/XP_BM, 256>>>(u, w_x, xdbl);

    // 5. dt_proj + fused softplus: delta = softplus(xdbl[:, :64] @ w_dt^T + b_dt)
    {
        dim3 g(DINNER/BN, ROWS/BM);
        sgemm_nt<<<g, 256>>>(xdbl, XPROJ_OUT, w_dt, DTRANK, delta, DINNER,
                             nullptr, 0, b_dt, ROWS, DINNER, DTRANK, 2);
    }

    // 6. selective scan (+ u*D_skip, fused gate with silu(z))
    scan_kernel<<<(BATCH*DINNER)/16, 256>>>(delta, u, xdbl, xz, A_log, Dsk, yg);

    // 7. out_proj + residual
    {
        dim3 g(DMODEL/BN, ROWS/BM);
        sgemm_nt<<<g, 256>>>(yg, DINNER, w_out, DINNER, out, DMODEL,
                             x, DMODEL, nullptr, ROWS, DMODEL, DINNER, 1);
    }
}